// round 3
// baseline (speedup 1.0000x reference)
#include <cuda_runtime.h>

#define GH 200
#define GW 200
#define GD 16
#define NVOX (GH * GW * GD)      // 640000
#define NCLS 18
#define NFEAT 17
#define KT 10                     // static tile cap, matches reference
#define VOXSZ 0.4f

__global__ __launch_bounds__(128) void gv_splat_kernel(
    const float* __restrict__ means,
    const float* __restrict__ opac,
    const float* __restrict__ feats,
    const float* __restrict__ scales,
    const float* __restrict__ rots,
    float* __restrict__ out,
    int ngauss)
{
    int n = blockIdx.x;
    if (n >= ngauss) return;

    const float lox = -40.f, loy = -40.f, loz = -1.f;
    const float hix =  40.f, hiy =  40.f, hiz =  5.4f;

    float mx = means[3 * n + 0];
    float my = means[3 * n + 1];
    float mz = means[3 * n + 2];

    float qw = rots[4 * n + 0];
    float qx = rots[4 * n + 1];
    float qy = rots[4 * n + 2];
    float qz = rots[4 * n + 3];
    float qn = rsqrtf(qw * qw + qx * qx + qy * qy + qz * qz);
    qw *= qn; qx *= qn; qy *= qn; qz *= qn;

    float r00 = 1.f - 2.f * (qy * qy + qz * qz);
    float r01 = 2.f * (qx * qy - qw * qz);
    float r02 = 2.f * (qx * qz + qw * qy);
    float r10 = 2.f * (qx * qy + qw * qz);
    float r11 = 1.f - 2.f * (qx * qx + qz * qz);
    float r12 = 2.f * (qy * qz - qw * qx);
    float r20 = 2.f * (qx * qz - qw * qy);
    float r21 = 2.f * (qy * qz + qw * qx);
    float r22 = 1.f - 2.f * (qx * qx + qy * qy);

    float s0 = scales[3 * n + 0];
    float s1 = scales[3 * n + 1];
    float s2 = scales[3 * n + 2];
    float i0 = 1.f / (s0 * s0);
    float i1 = 1.f / (s1 * s1);
    float i2 = 1.f / (s2 * s2);

    // cov_inv = R diag(1/s^2) R^T (symmetric)
    float m00 = r00 * r00 * i0 + r01 * r01 * i1 + r02 * r02 * i2;
    float m01 = r00 * r10 * i0 + r01 * r11 * i1 + r02 * r12 * i2;
    float m02 = r00 * r20 * i0 + r01 * r21 * i1 + r02 * r22 * i2;
    float m11 = r10 * r10 * i0 + r11 * r11 * i1 + r12 * r12 * i2;
    float m12 = r10 * r20 * i0 + r11 * r21 * i1 + r12 * r22 * i2;
    float m22 = r20 * r20 * i0 + r21 * r21 * i1 + r22 * r22 * i2;

    // sigma = sqrt(diag(cov)), diag(cov)_a = sum_k (R_ak s_k)^2
    float sigx = sqrtf(r00 * r00 * s0 * s0 + r01 * r01 * s1 * s1 + r02 * r02 * s2 * s2);
    float sigy = sqrtf(r10 * r10 * s0 * s0 + r11 * r11 * s1 * s1 + r12 * r12 * s2 * s2);
    float sigz = sqrtf(r20 * r20 * s0 * s0 + r21 * r21 * s1 * s1 + r22 * r22 * s2 * s2);

    float blox = fminf(fmaxf(mx - 3.f * sigx, lox), hix);
    float bloy = fminf(fmaxf(my - 3.f * sigy, loy), hiy);
    float bloz = fminf(fmaxf(mz - 3.f * sigz, loz), hiz);
    float bhix = fminf(fmaxf(mx + 3.f * sigx, lox), hix);
    float bhiy = fminf(fmaxf(my + 3.f * sigy, loy), hiy);
    float bhiz = fminf(fmaxf(mz + 3.f * sigz, loz), hiz);

    bool valid =
        ((blox > lox) || (bhix > lox)) && ((blox < hix) || (bhix < hix)) &&
        ((bloy > loy) || (bhiy > loy)) && ((bloy < hiy) || (bhiy < hiy)) &&
        ((bloz > loz) || (bhiz > loz)) && ((bloz < hiz) || (bhiz < hiz));
    if (!valid) return;

    int ilox = (int)((blox - lox) / VOXSZ);
    int iloy = (int)((bloy - loy) / VOXSZ);
    int iloz = (int)((bloz - loz) / VOXSZ);
    int ihix = (int)((bhix - lox) / VOXSZ);
    int ihiy = (int)((bhiy - loy) / VOXSZ);
    int ihiz = (int)((bhiz - loz) / VOXSZ);

    int exi = min(min(ihix, ilox + KT - 1), GH - 1);
    int eyi = min(min(ihiy, iloy + KT - 1), GW - 1);
    int ezi = min(min(ihiz, iloz + KT - 1), GD - 1);
    int nx = exi - ilox + 1;
    int ny = eyi - iloy + 1;
    int nz = ezi - iloz + 1;
    if (nx <= 0 || ny <= 0 || nz <= 0) return;

    float op = opac[n];

    float fc[NFEAT];
#pragma unroll
    for (int c = 0; c < NFEAT; c++) fc[c] = feats[n * NFEAT + c];

    int total = nx * ny * nz;
    for (int t = threadIdx.x; t < total; t += blockDim.x) {
        int kz  = t % nz;
        int rem = t / nz;
        int jy  = rem % ny;
        int ix  = rem / ny;
        int vi = ilox + ix;
        int vj = iloy + jy;
        int vk = iloz + kz;

        float cx = (vi + 0.5f) * VOXSZ + lox;
        float cy = (vj + 0.5f) * VOXSZ + loy;
        float cz = (vk + 0.5f) * VOXSZ + loz;
        float dx = cx - mx;
        float dy = cy - my;
        float dz = cz - mz;

        float maha = m00 * dx * dx + m11 * dy * dy + m22 * dz * dz
                   + 2.f * (m01 * dx * dy + m02 * dx * dz + m12 * dy * dz);
        float dens = op * __expf(-0.5f * maha);

        if (dens > 1e-12f) {
            int flat = (vi * GW + vj) * GD + vk;
            atomicAdd(&out[flat], dens);
            float* fo = out + NVOX + (size_t)flat * NCLS;
#pragma unroll
            for (int c = 0; c < NFEAT; c++)
                atomicAdd(&fo[c], dens * fc[c]);
            // class 17 contribution is identically zero -> skip
        }
    }
}

__global__ __launch_bounds__(256) void gv_finalize_kernel(
    float* __restrict__ out,
    const float* __restrict__ empty_scalar)
{
    int v = blockIdx.x * blockDim.x + threadIdx.x;
    if (v >= NVOX) return;

    int vk = v % GD;
    int vj = (v / GD) % GW;
    int vi = v / (GD * GW);

    // voxel center
    float cx = (vi + 0.5f) * VOXSZ - 40.f;
    float cy = (vj + 0.5f) * VOXSZ - 40.f;
    float cz = (vk + 0.5f) * VOXSZ - 1.f;

    // empty gaussian: mean = (0, 0, 2.2), inv cov = diag(1/range^2), range = (80, 80, 6.4)
    float dx = cx * (1.f / 80.f);
    float dy = cy * (1.f / 80.f);
    float dz = (cz - 2.2f) * (1.f / 6.4f);
    float maha_e = dx * dx + dy * dy + dz * dz;
    float dens_e = __expf(-0.5f * maha_e);

    float gd = out[v] + dens_e;
    out[v] = gd;
    float inv = 1.f / fmaxf(gd, 1e-6f);

    float* f = out + NVOX + (size_t)v * NCLS;
#pragma unroll
    for (int c = 0; c < NFEAT; c++)
        f[c] = f[c] * inv;
    // class 17: accumulated part is zero; only empty gaussian contributes
    f[NFEAT] = dens_e * empty_scalar[0] * inv;
}

extern "C" void kernel_launch(void* const* d_in, const int* in_sizes, int n_in,
                              void* d_out, int out_size)
{
    const float* means  = (const float*)d_in[0];
    const float* opac   = (const float*)d_in[1];
    const float* feats  = (const float*)d_in[2];
    const float* scales = (const float*)d_in[3];
    const float* rots   = (const float*)d_in[4];
    const float* es     = (const float*)d_in[5];
    float* out = (float*)d_out;

    int ngauss = in_sizes[0] / 3;

    cudaMemsetAsync(d_out, 0, (size_t)out_size * sizeof(float), 0);

    gv_splat_kernel<<<ngauss, 128>>>(means, opac, feats, scales, rots, out, ngauss);

    gv_finalize_kernel<<<(NVOX + 255) / 256, 256>>>(out, es);
}

// round 4
// speedup vs baseline: 2.5130x; 2.5130x over previous
#include <cuda_runtime.h>

#define GH 200
#define GW 200
#define GD 16
#define NVOX (GH * GW * GD)      // 640000
#define NCLS 18
#define NFEAT 17
#define KT 10
#define VOXSZ 0.4f
#define REC 20                    // padded floats per voxel record (80B, 16B aligned)

// Scratch accumulator: per voxel [f0..f15][f16][dens][pad][pad].
// Zero-initialized BSS; every finalize pass restores it to zero, so graph
// replays see identical initial state. 640000*20*4 = 51.2 MB.
__device__ __align__(16) float g_scratch[(size_t)NVOX * REC];

__device__ __forceinline__ void red_v4(float* p, float a, float b, float c, float d) {
    asm volatile("red.global.add.v4.f32 [%0], {%1, %2, %3, %4};"
                 :: "l"(p), "f"(a), "f"(b), "f"(c), "f"(d) : "memory");
}
__device__ __forceinline__ void red_v2(float* p, float a, float b) {
    asm volatile("red.global.add.v2.f32 [%0], {%1, %2};"
                 :: "l"(p), "f"(a), "f"(b) : "memory");
}

__global__ __launch_bounds__(128) void gv_splat_kernel(
    const float* __restrict__ means,
    const float* __restrict__ opac,
    const float* __restrict__ feats,
    const float* __restrict__ scales,
    const float* __restrict__ rots,
    int ngauss)
{
    int n = blockIdx.x;
    if (n >= ngauss) return;

    const float lox = -40.f, loy = -40.f, loz = -1.f;
    const float hix =  40.f, hiy =  40.f, hiz =  5.4f;

    float mx = means[3 * n + 0];
    float my = means[3 * n + 1];
    float mz = means[3 * n + 2];

    float qw = rots[4 * n + 0];
    float qx = rots[4 * n + 1];
    float qy = rots[4 * n + 2];
    float qz = rots[4 * n + 3];
    float qn = rsqrtf(qw * qw + qx * qx + qy * qy + qz * qz);
    qw *= qn; qx *= qn; qy *= qn; qz *= qn;

    float r00 = 1.f - 2.f * (qy * qy + qz * qz);
    float r01 = 2.f * (qx * qy - qw * qz);
    float r02 = 2.f * (qx * qz + qw * qy);
    float r10 = 2.f * (qx * qy + qw * qz);
    float r11 = 1.f - 2.f * (qx * qx + qz * qz);
    float r12 = 2.f * (qy * qz - qw * qx);
    float r20 = 2.f * (qx * qz - qw * qy);
    float r21 = 2.f * (qy * qz + qw * qx);
    float r22 = 1.f - 2.f * (qx * qx + qy * qy);

    float s0 = scales[3 * n + 0];
    float s1 = scales[3 * n + 1];
    float s2 = scales[3 * n + 2];
    float i0 = 1.f / (s0 * s0);
    float i1 = 1.f / (s1 * s1);
    float i2 = 1.f / (s2 * s2);

    // cov_inv = R diag(1/s^2) R^T (symmetric)
    float m00 = r00 * r00 * i0 + r01 * r01 * i1 + r02 * r02 * i2;
    float m01 = r00 * r10 * i0 + r01 * r11 * i1 + r02 * r12 * i2;
    float m02 = r00 * r20 * i0 + r01 * r21 * i1 + r02 * r22 * i2;
    float m11 = r10 * r10 * i0 + r11 * r11 * i1 + r12 * r12 * i2;
    float m12 = r10 * r20 * i0 + r11 * r21 * i1 + r12 * r22 * i2;
    float m22 = r20 * r20 * i0 + r21 * r21 * i1 + r22 * r22 * i2;

    float sigx = sqrtf(r00 * r00 * s0 * s0 + r01 * r01 * s1 * s1 + r02 * r02 * s2 * s2);
    float sigy = sqrtf(r10 * r10 * s0 * s0 + r11 * r11 * s1 * s1 + r12 * r12 * s2 * s2);
    float sigz = sqrtf(r20 * r20 * s0 * s0 + r21 * r21 * s1 * s1 + r22 * r22 * s2 * s2);

    float blox = fminf(fmaxf(mx - 3.f * sigx, lox), hix);
    float bloy = fminf(fmaxf(my - 3.f * sigy, loy), hiy);
    float bloz = fminf(fmaxf(mz - 3.f * sigz, loz), hiz);
    float bhix = fminf(fmaxf(mx + 3.f * sigx, lox), hix);
    float bhiy = fminf(fmaxf(my + 3.f * sigy, loy), hiy);
    float bhiz = fminf(fmaxf(mz + 3.f * sigz, loz), hiz);

    bool valid =
        ((blox > lox) || (bhix > lox)) && ((blox < hix) || (bhix < hix)) &&
        ((bloy > loy) || (bhiy > loy)) && ((bloy < hiy) || (bhiy < hiy)) &&
        ((bloz > loz) || (bhiz > loz)) && ((bloz < hiz) || (bhiz < hiz));
    if (!valid) return;

    int ilox = (int)((blox - lox) / VOXSZ);
    int iloy = (int)((bloy - loy) / VOXSZ);
    int iloz = (int)((bloz - loz) / VOXSZ);
    int ihix = (int)((bhix - lox) / VOXSZ);
    int ihiy = (int)((bhiy - loy) / VOXSZ);
    int ihiz = (int)((bhiz - loz) / VOXSZ);

    int exi = min(min(ihix, ilox + KT - 1), GH - 1);
    int eyi = min(min(ihiy, iloy + KT - 1), GW - 1);
    int ezi = min(min(ihiz, iloz + KT - 1), GD - 1);
    int nx = exi - ilox + 1;
    int ny = eyi - iloy + 1;
    int nz = ezi - iloz + 1;
    if (nx <= 0 || ny <= 0 || nz <= 0) return;

    float op = opac[n];

    float fc[NFEAT];
#pragma unroll
    for (int c = 0; c < NFEAT; c++) fc[c] = feats[n * NFEAT + c];

    int total = nx * ny * nz;
    for (int t = threadIdx.x; t < total; t += blockDim.x) {
        int kz  = t % nz;
        int rem = t / nz;
        int jy  = rem % ny;
        int ix  = rem / ny;
        int vi = ilox + ix;
        int vj = iloy + jy;
        int vk = iloz + kz;

        float dx = (vi + 0.5f) * VOXSZ + lox - mx;
        float dy = (vj + 0.5f) * VOXSZ + loy - my;
        float dz = (vk + 0.5f) * VOXSZ + loz - mz;

        float maha = m00 * dx * dx + m11 * dy * dy + m22 * dz * dz
                   + 2.f * (m01 * dx * dy + m02 * dx * dz + m12 * dy * dz);
        float dens = op * __expf(-0.5f * maha);

        if (dens > 1e-12f) {
            int flat = (vi * GW + vj) * GD + vk;
            float* rec = g_scratch + (size_t)flat * REC;
            red_v4(rec +  0, dens * fc[0],  dens * fc[1],  dens * fc[2],  dens * fc[3]);
            red_v4(rec +  4, dens * fc[4],  dens * fc[5],  dens * fc[6],  dens * fc[7]);
            red_v4(rec +  8, dens * fc[8],  dens * fc[9],  dens * fc[10], dens * fc[11]);
            red_v4(rec + 12, dens * fc[12], dens * fc[13], dens * fc[14], dens * fc[15]);
            red_v2(rec + 16, dens * fc[16], dens);
            // class 17 contribution is identically zero -> skip
        }
    }
}

#define FB_VOX 64   // voxels per finalize block

__global__ __launch_bounds__(256) void gv_finalize_kernel(
    float* __restrict__ out,
    const float* __restrict__ empty_scalar)
{
    __shared__ float s[FB_VOX * REC];
    __shared__ float s_inv[FB_VOX];
    __shared__ float s_gd[FB_VOX];
    __shared__ float s_de[FB_VOX];

    int vb = blockIdx.x * FB_VOX;   // NVOX % FB_VOX == 0

    // coalesced stage-in of 64 voxel records
    for (int idx = threadIdx.x; idx < FB_VOX * REC; idx += 256)
        s[idx] = g_scratch[(size_t)vb * REC + idx];
    __syncthreads();

    if (threadIdx.x < FB_VOX) {
        int v = vb + threadIdx.x;
        int vk = v % GD;
        int vj = (v / GD) % GW;
        int vi = v / (GD * GW);

        float cx = (vi + 0.5f) * VOXSZ - 40.f;
        float cy = (vj + 0.5f) * VOXSZ - 40.f;
        float cz = (vk + 0.5f) * VOXSZ - 1.f;

        // empty gaussian: mean (0,0,2.2), inv cov = diag(1/range^2), range (80,80,6.4)
        float ex = cx * (1.f / 80.f);
        float ey = cy * (1.f / 80.f);
        float ez = (cz - 2.2f) * (1.f / 6.4f);
        float dens_e = __expf(-0.5f * (ex * ex + ey * ey + ez * ez));

        float gd = s[threadIdx.x * REC + 17] + dens_e;
        s_gd[threadIdx.x]  = gd;
        s_de[threadIdx.x]  = dens_e;
        s_inv[threadIdx.x] = 1.f / fmaxf(gd, 1e-6f);
    }
    __syncthreads();

    if (threadIdx.x < FB_VOX)
        out[vb + threadIdx.x] = s_gd[threadIdx.x];

    float esc = empty_scalar[0];

    // coalesced feature writes: 64*18 elements
    for (int idx = threadIdx.x; idx < FB_VOX * NCLS; idx += 256) {
        int vl = idx / NCLS;
        int c  = idx - vl * NCLS;
        float val = (c < NFEAT) ? s[vl * REC + c] : s_de[vl] * esc;
        out[NVOX + (size_t)vb * NCLS + idx] = val * s_inv[vl];
    }

    // restore scratch to zero for the next graph replay
    for (int idx = threadIdx.x; idx < FB_VOX * REC; idx += 256)
        g_scratch[(size_t)vb * REC + idx] = 0.f;
}

extern "C" void kernel_launch(void* const* d_in, const int* in_sizes, int n_in,
                              void* d_out, int out_size)
{
    const float* means  = (const float*)d_in[0];
    const float* opac   = (const float*)d_in[1];
    const float* feats  = (const float*)d_in[2];
    const float* scales = (const float*)d_in[3];
    const float* rots   = (const float*)d_in[4];
    const float* es     = (const float*)d_in[5];
    float* out = (float*)d_out;

    int ngauss = in_sizes[0] / 3;

    gv_splat_kernel<<<ngauss, 128>>>(means, opac, feats, scales, rots, ngauss);

    gv_finalize_kernel<<<NVOX / FB_VOX, 256>>>(out, es);
}

// round 6
// speedup vs baseline: 2.8256x; 1.1244x over previous
#include <cuda_runtime.h>

#define GH 200
#define GW 200
#define GD 16
#define NVOX (GH * GW * GD)      // 640000
#define NCLS 18
#define NFEAT 17
#define KT 10
#define VOXSZ 0.4f
#define REC 20                    // padded floats per voxel record (80B, 16B aligned)

// Scratch accumulator: per voxel [f0..f15][f16][dens][pad][pad].
// Zeroed by a memset node at the start of every launch. 640000*20*4 = 51.2 MB
// (fits in the 126 MB L2, so reds + finalize reads mostly stay on-die).
__device__ __align__(16) float g_scratch[(size_t)NVOX * REC];

__device__ __forceinline__ void red_v4(float* p, float a, float b, float c, float d) {
    asm volatile("red.global.add.v4.f32 [%0], {%1, %2, %3, %4};"
                 :: "l"(p), "f"(a), "f"(b), "f"(c), "f"(d) : "memory");
}
__device__ __forceinline__ void red_v2(float* p, float a, float b) {
    asm volatile("red.global.add.v2.f32 [%0], {%1, %2};"
                 :: "l"(p), "f"(a), "f"(b) : "memory");
}

__global__ __launch_bounds__(128) void gv_splat_kernel(
    const float* __restrict__ means,
    const float* __restrict__ opac,
    const float* __restrict__ feats,
    const float* __restrict__ scales,
    const float* __restrict__ rots,
    int ngauss)
{
    int n = blockIdx.x;
    if (n >= ngauss) return;

    const float lox = -40.f, loy = -40.f, loz = -1.f;
    const float hix =  40.f, hiy =  40.f, hiz =  5.4f;

    float mx = means[3 * n + 0];
    float my = means[3 * n + 1];
    float mz = means[3 * n + 2];

    float qw = rots[4 * n + 0];
    float qx = rots[4 * n + 1];
    float qy = rots[4 * n + 2];
    float qz = rots[4 * n + 3];
    float qn = rsqrtf(qw * qw + qx * qx + qy * qy + qz * qz);
    qw *= qn; qx *= qn; qy *= qn; qz *= qn;

    float r00 = 1.f - 2.f * (qy * qy + qz * qz);
    float r01 = 2.f * (qx * qy - qw * qz);
    float r02 = 2.f * (qx * qz + qw * qy);
    float r10 = 2.f * (qx * qy + qw * qz);
    float r11 = 1.f - 2.f * (qx * qx + qz * qz);
    float r12 = 2.f * (qy * qz - qw * qx);
    float r20 = 2.f * (qx * qz - qw * qy);
    float r21 = 2.f * (qy * qz + qw * qx);
    float r22 = 1.f - 2.f * (qx * qx + qy * qy);

    float s0 = scales[3 * n + 0];
    float s1 = scales[3 * n + 1];
    float s2 = scales[3 * n + 2];
    float i0 = 1.f / (s0 * s0);
    float i1 = 1.f / (s1 * s1);
    float i2 = 1.f / (s2 * s2);

    // cov_inv = R diag(1/s^2) R^T (symmetric)
    float m00 = r00 * r00 * i0 + r01 * r01 * i1 + r02 * r02 * i2;
    float m01 = r00 * r10 * i0 + r01 * r11 * i1 + r02 * r12 * i2;
    float m02 = r00 * r20 * i0 + r01 * r21 * i1 + r02 * r22 * i2;
    float m11 = r10 * r10 * i0 + r11 * r11 * i1 + r12 * r12 * i2;
    float m12 = r10 * r20 * i0 + r11 * r21 * i1 + r12 * r22 * i2;
    float m22 = r20 * r20 * i0 + r21 * r21 * i1 + r22 * r22 * i2;

    float sigx = sqrtf(r00 * r00 * s0 * s0 + r01 * r01 * s1 * s1 + r02 * r02 * s2 * s2);
    float sigy = sqrtf(r10 * r10 * s0 * s0 + r11 * r11 * s1 * s1 + r12 * r12 * s2 * s2);
    float sigz = sqrtf(r20 * r20 * s0 * s0 + r21 * r21 * s1 * s1 + r22 * r22 * s2 * s2);

    float blox = fminf(fmaxf(mx - 3.f * sigx, lox), hix);
    float bloy = fminf(fmaxf(my - 3.f * sigy, loy), hiy);
    float bloz = fminf(fmaxf(mz - 3.f * sigz, loz), hiz);
    float bhix = fminf(fmaxf(mx + 3.f * sigx, lox), hix);
    float bhiy = fminf(fmaxf(my + 3.f * sigy, loy), hiy);
    float bhiz = fminf(fmaxf(mz + 3.f * sigz, loz), hiz);

    bool valid =
        ((blox > lox) || (bhix > lox)) && ((blox < hix) || (bhix < hix)) &&
        ((bloy > loy) || (bhiy > loy)) && ((bloy < hiy) || (bhiy < hiy)) &&
        ((bloz > loz) || (bhiz > loz)) && ((bloz < hiz) || (bhiz < hiz));
    if (!valid) return;

    int ilox = (int)((blox - lox) / VOXSZ);
    int iloy = (int)((bloy - loy) / VOXSZ);
    int iloz = (int)((bloz - loz) / VOXSZ);
    int ihix = (int)((bhix - lox) / VOXSZ);
    int ihiy = (int)((bhiy - loy) / VOXSZ);
    int ihiz = (int)((bhiz - loz) / VOXSZ);

    int exi = min(min(ihix, ilox + KT - 1), GH - 1);
    int eyi = min(min(ihiy, iloy + KT - 1), GW - 1);
    int ezi = min(min(ihiz, iloz + KT - 1), GD - 1);
    int nx = exi - ilox + 1;
    int ny = eyi - iloy + 1;
    int nz = ezi - iloz + 1;
    if (nx <= 0 || ny <= 0 || nz <= 0) return;

    float op = opac[n];

    float fc[NFEAT];
#pragma unroll
    for (int c = 0; c < NFEAT; c++) fc[c] = feats[n * NFEAT + c];

    int total = nx * ny * nz;
    for (int t = threadIdx.x; t < total; t += blockDim.x) {
        int kz  = t % nz;
        int rem = t / nz;
        int jy  = rem % ny;
        int ix  = rem / ny;
        int vi = ilox + ix;
        int vj = iloy + jy;
        int vk = iloz + kz;

        float dx = (vi + 0.5f) * VOXSZ + lox - mx;
        float dy = (vj + 0.5f) * VOXSZ + loy - my;
        float dz = (vk + 0.5f) * VOXSZ + loz - mz;

        float maha = m00 * dx * dx + m11 * dy * dy + m22 * dz * dz
                   + 2.f * (m01 * dx * dy + m02 * dx * dz + m12 * dy * dz);
        float dens = op * __expf(-0.5f * maha);

        // empty-gaussian floor guarantees total density >= ~0.69 everywhere,
        // so skipping contributions < 1e-7 bounds rel err at ~1e-6.
        if (dens > 1e-7f) {
            int flat = (vi * GW + vj) * GD + vk;
            float* rec = g_scratch + (size_t)flat * REC;
            red_v4(rec +  0, dens * fc[0],  dens * fc[1],  dens * fc[2],  dens * fc[3]);
            red_v4(rec +  4, dens * fc[4],  dens * fc[5],  dens * fc[6],  dens * fc[7]);
            red_v4(rec +  8, dens * fc[8],  dens * fc[9],  dens * fc[10], dens * fc[11]);
            red_v4(rec + 12, dens * fc[12], dens * fc[13], dens * fc[14], dens * fc[15]);
            red_v2(rec + 16, dens * fc[16], dens);
            // class 17 contribution is identically zero -> skip
        }
    }
}

#define FB_VOX 64   // voxels per finalize block

__global__ __launch_bounds__(256) void gv_finalize_kernel(
    float* __restrict__ out,
    const float* __restrict__ empty_scalar)
{
    __shared__ float4 s4[FB_VOX * REC / 4];   // 320 x float4
    __shared__ float s_inv[FB_VOX];
    __shared__ float s_gd[FB_VOX];
    __shared__ float s_de[FB_VOX];
    float* s = (float*)s4;

    int vb = blockIdx.x * FB_VOX;   // NVOX % FB_VOX == 0

    // coalesced float4 stage-in of 64 voxel records (320 float4s)
    const float4* g4 = (const float4*)(g_scratch + (size_t)vb * REC);
    for (int idx = threadIdx.x; idx < FB_VOX * REC / 4; idx += 256)
        s4[idx] = g4[idx];
    __syncthreads();

    if (threadIdx.x < FB_VOX) {
        int v = vb + threadIdx.x;
        int vk = v % GD;
        int vj = (v / GD) % GW;
        int vi = v / (GD * GW);

        float cx = (vi + 0.5f) * VOXSZ - 40.f;
        float cy = (vj + 0.5f) * VOXSZ - 40.f;
        float cz = (vk + 0.5f) * VOXSZ - 1.f;

        // empty gaussian: mean (0,0,2.2), inv cov = diag(1/range^2), range (80,80,6.4)
        float ex = cx * (1.f / 80.f);
        float ey = cy * (1.f / 80.f);
        float ez = (cz - 2.2f) * (1.f / 6.4f);
        float dens_e = __expf(-0.5f * (ex * ex + ey * ey + ez * ez));

        float gd = s[threadIdx.x * REC + 17] + dens_e;
        s_gd[threadIdx.x]  = gd;
        s_de[threadIdx.x]  = dens_e;
        s_inv[threadIdx.x] = 1.f / fmaxf(gd, 1e-6f);
    }
    __syncthreads();

    // density: 64 floats = 16 float4 stores (out+vb is 256B aligned)
    if (threadIdx.x < FB_VOX / 4) {
        float4 d4 = make_float4(s_gd[4 * threadIdx.x + 0], s_gd[4 * threadIdx.x + 1],
                                s_gd[4 * threadIdx.x + 2], s_gd[4 * threadIdx.x + 3]);
        ((float4*)(out + vb))[threadIdx.x] = d4;
    }

    float esc = empty_scalar[0];

    // features: 64*18 = 1152 floats = 288 float4 stores, base 16B-aligned
    float4* o4 = (float4*)(out + NVOX + (size_t)vb * NCLS);
    for (int q = threadIdx.x; q < FB_VOX * NCLS / 4; q += 256) {
        int o  = 4 * q;
        int vl = (unsigned)o / 18u;
        int c0 = o - vl * 18;
        float r[4];
#pragma unroll
        for (int j = 0; j < 4; j++) {
            int vv = vl, cc = c0 + j;
            if (cc >= NCLS) { vv++; cc -= NCLS; }
            float val = (cc < NFEAT) ? s[vv * REC + cc] : s_de[vv] * esc;
            r[j] = val * s_inv[vv];
        }
        o4[q] = make_float4(r[0], r[1], r[2], r[3]);
    }
}

extern "C" void kernel_launch(void* const* d_in, const int* in_sizes, int n_in,
                              void* d_out, int out_size)
{
    const float* means  = (const float*)d_in[0];
    const float* opac   = (const float*)d_in[1];
    const float* feats  = (const float*)d_in[2];
    const float* scales = (const float*)d_in[3];
    const float* rots   = (const float*)d_in[4];
    const float* es     = (const float*)d_in[5];
    float* out = (float*)d_out;

    int ngauss = in_sizes[0] / 3;

    // zero the scratch accumulator (graph-capturable memset node)
    void* sptr = nullptr;
    cudaGetSymbolAddress(&sptr, g_scratch);
    cudaMemsetAsync(sptr, 0, sizeof(float) * (size_t)NVOX * REC, 0);

    gv_splat_kernel<<<ngauss, 128>>>(means, opac, feats, scales, rots, ngauss);

    gv_finalize_kernel<<<NVOX / FB_VOX, 256>>>(out, es);
}

// round 7
// speedup vs baseline: 2.8407x; 1.0053x over previous
#include <cuda_runtime.h>

#define GH 200
#define GW 200
#define GD 16
#define NVOX (GH * GW * GD)      // 640000
#define NCLS 18
#define NFEAT 17
#define KT 10
#define VOXSZ 0.4f
#define REC 20                    // padded floats per voxel record (80B, 16B aligned)

// Scratch accumulator: per voxel [f0..f16][dens at 17][pad][pad].
// Zeroed by a memset node at the start of every launch. 51.2 MB.
__device__ __align__(16) float g_scratch[(size_t)NVOX * REC];

__device__ __forceinline__ void red_v4(float* p, float a, float b, float c, float d) {
    asm volatile("red.global.add.v4.f32 [%0], {%1, %2, %3, %4};"
                 :: "l"(p), "f"(a), "f"(b), "f"(c), "f"(d) : "memory");
}
__device__ __forceinline__ void red_v2(float* p, float a, float b) {
    asm volatile("red.global.add.v2.f32 [%0], {%1, %2};"
                 :: "l"(p), "f"(a), "f"(b) : "memory");
}

// one warp per gaussian, 4 warps per block
__global__ __launch_bounds__(128) void gv_splat_kernel(
    const float* __restrict__ means,
    const float* __restrict__ opac,
    const float* __restrict__ feats,
    const float* __restrict__ scales,
    const float* __restrict__ rots,
    int ngauss)
{
    int n = blockIdx.x * 4 + (threadIdx.x >> 5);
    if (n >= ngauss) return;
    int lane = threadIdx.x & 31;

    const float lox = -40.f, loy = -40.f, loz = -1.f;
    const float hix =  40.f, hiy =  40.f, hiz =  5.4f;

    float mx = means[3 * n + 0];
    float my = means[3 * n + 1];
    float mz = means[3 * n + 2];

    float qw = rots[4 * n + 0];
    float qx = rots[4 * n + 1];
    float qy = rots[4 * n + 2];
    float qz = rots[4 * n + 3];
    float qn = rsqrtf(qw * qw + qx * qx + qy * qy + qz * qz);
    qw *= qn; qx *= qn; qy *= qn; qz *= qn;

    float r00 = 1.f - 2.f * (qy * qy + qz * qz);
    float r01 = 2.f * (qx * qy - qw * qz);
    float r02 = 2.f * (qx * qz + qw * qy);
    float r10 = 2.f * (qx * qy + qw * qz);
    float r11 = 1.f - 2.f * (qx * qx + qz * qz);
    float r12 = 2.f * (qy * qz - qw * qx);
    float r20 = 2.f * (qx * qz - qw * qy);
    float r21 = 2.f * (qy * qz + qw * qx);
    float r22 = 1.f - 2.f * (qx * qx + qy * qy);

    float s0 = scales[3 * n + 0];
    float s1 = scales[3 * n + 1];
    float s2 = scales[3 * n + 2];
    float i0 = 1.f / (s0 * s0);
    float i1 = 1.f / (s1 * s1);
    float i2 = 1.f / (s2 * s2);

    // cov_inv = R diag(1/s^2) R^T (symmetric), cross terms pre-doubled
    float m00 = r00 * r00 * i0 + r01 * r01 * i1 + r02 * r02 * i2;
    float m11 = r10 * r10 * i0 + r11 * r11 * i1 + r12 * r12 * i2;
    float m22 = r20 * r20 * i0 + r21 * r21 * i1 + r22 * r22 * i2;
    float m01 = 2.f * (r00 * r10 * i0 + r01 * r11 * i1 + r02 * r12 * i2);
    float m02 = 2.f * (r00 * r20 * i0 + r01 * r21 * i1 + r02 * r22 * i2);
    float m12 = 2.f * (r10 * r20 * i0 + r11 * r21 * i1 + r12 * r22 * i2);

    float sigx = sqrtf(r00 * r00 * s0 * s0 + r01 * r01 * s1 * s1 + r02 * r02 * s2 * s2);
    float sigy = sqrtf(r10 * r10 * s0 * s0 + r11 * r11 * s1 * s1 + r12 * r12 * s2 * s2);
    float sigz = sqrtf(r20 * r20 * s0 * s0 + r21 * r21 * s1 * s1 + r22 * r22 * s2 * s2);

    float blox = fminf(fmaxf(mx - 3.f * sigx, lox), hix);
    float bloy = fminf(fmaxf(my - 3.f * sigy, loy), hiy);
    float bloz = fminf(fmaxf(mz - 3.f * sigz, loz), hiz);
    float bhix = fminf(fmaxf(mx + 3.f * sigx, lox), hix);
    float bhiy = fminf(fmaxf(my + 3.f * sigy, loy), hiy);
    float bhiz = fminf(fmaxf(mz + 3.f * sigz, loz), hiz);

    bool valid =
        ((blox > lox) || (bhix > lox)) && ((blox < hix) || (bhix < hix)) &&
        ((bloy > loy) || (bhiy > loy)) && ((bloy < hiy) || (bhiy < hiy)) &&
        ((bloz > loz) || (bhiz > loz)) && ((bloz < hiz) || (bhiz < hiz));
    if (!valid) return;

    int ilox = (int)((blox - lox) / VOXSZ);
    int iloy = (int)((bloy - loy) / VOXSZ);
    int iloz = (int)((bloz - loz) / VOXSZ);
    int ihix = (int)((bhix - lox) / VOXSZ);
    int ihiy = (int)((bhiy - loy) / VOXSZ);
    int ihiz = (int)((bhiz - loz) / VOXSZ);

    int exi = min(min(ihix, ilox + KT - 1), GH - 1);
    int eyi = min(min(ihiy, iloy + KT - 1), GW - 1);
    int ezi = min(min(ihiz, iloz + KT - 1), GD - 1);
    int nx = exi - ilox + 1;
    int ny = eyi - iloy + 1;
    int nz = ezi - iloz + 1;
    if (nx <= 0 || ny <= 0 || nz <= 0) return;

    float op = opac[n];
    // dens > 1e-7  <=>  maha < 2*ln(op*1e7); negative thr -> everything skips
    float thr = 2.f * __logf(op * 1e7f);

    float fc[NFEAT];
#pragma unroll
    for (int c = 0; c < NFEAT; c++) fc[c] = feats[n * NFEAT + c];

    int total = nx * ny * nz;
    for (int t = lane; t < total; t += 32) {
        int kz  = t % nz;
        int rem = t / nz;
        int jy  = rem % ny;
        int ix  = rem / ny;
        int vi = ilox + ix;
        int vj = iloy + jy;
        int vk = iloz + kz;

        float dx = (vi + 0.5f) * VOXSZ + lox - mx;
        float dy = (vj + 0.5f) * VOXSZ + loy - my;
        float dz = (vk + 0.5f) * VOXSZ + loz - mz;

        float maha = m00 * dx * dx + m11 * dy * dy + m22 * dz * dz
                   + m01 * dx * dy + m02 * dx * dz + m12 * dy * dz;

        if (maha < thr) {
            float dens = op * __expf(-0.5f * maha);
            int flat = (vi * GW + vj) * GD + vk;
            float* rec = g_scratch + (size_t)flat * REC;
            red_v4(rec +  0, dens * fc[0],  dens * fc[1],  dens * fc[2],  dens * fc[3]);
            red_v4(rec +  4, dens * fc[4],  dens * fc[5],  dens * fc[6],  dens * fc[7]);
            red_v4(rec +  8, dens * fc[8],  dens * fc[9],  dens * fc[10], dens * fc[11]);
            red_v4(rec + 12, dens * fc[12], dens * fc[13], dens * fc[14], dens * fc[15]);
            red_v2(rec + 16, dens * fc[16], dens);
            // class 17 contribution is identically zero -> skip
        }
    }
}

#define FB_VOX 64    // voxels per finalize block
#define FB_THR 320   // = FB_VOX*REC/4 : one float4 stage-in per thread

__global__ __launch_bounds__(FB_THR) void gv_finalize_kernel(
    float* __restrict__ out,
    const float* __restrict__ empty_scalar)
{
    __shared__ float4 s4[FB_THR];         // 64 records x 20 floats
    __shared__ float s_inv[FB_VOX];
    __shared__ float s_gd[FB_VOX];
    __shared__ float s_de[FB_VOX];
    float* s = (float*)s4;

    int vb  = blockIdx.x * FB_VOX;        // NVOX % FB_VOX == 0
    int tid = threadIdx.x;

    // exactly one coalesced float4 stage-in per thread
    const float4* g4 = (const float4*)(g_scratch + (size_t)vb * REC);
    s4[tid] = g4[tid];

    // per-voxel inverse: reads dens straight from GLOBAL (L2-resident),
    // independent of the smem staging -> only one barrier needed
    if (tid < FB_VOX) {
        int v = vb + tid;
        int vk = v % GD;
        int vj = (v / GD) % GW;
        int vi = v / (GD * GW);

        float cx = (vi + 0.5f) * VOXSZ - 40.f;
        float cy = (vj + 0.5f) * VOXSZ - 40.f;
        float cz = (vk + 0.5f) * VOXSZ - 1.f;

        // empty gaussian: mean (0,0,2.2), inv cov = diag(1/range^2), range (80,80,6.4)
        float ex = cx * (1.f / 80.f);
        float ey = cy * (1.f / 80.f);
        float ez = (cz - 2.2f) * (1.f / 6.4f);
        float dens_e = __expf(-0.5f * (ex * ex + ey * ey + ez * ez));

        float gd = g_scratch[(size_t)v * REC + 17] + dens_e;
        s_gd[tid]  = gd;
        s_de[tid]  = dens_e;
        s_inv[tid] = __fdividef(1.f, fmaxf(gd, 1e-6f));
    }
    __syncthreads();

    float esc = empty_scalar[0];

    if (tid < FB_VOX * NCLS / 4) {
        // features: 288 float4 stores, base 16B-aligned
        int o  = 4 * tid;
        int vl = (unsigned)o / 18u;
        int c0 = o - vl * 18;
        float r[4];
#pragma unroll
        for (int j = 0; j < 4; j++) {
            int vv = vl, cc = c0 + j;
            if (cc >= NCLS) { vv++; cc -= NCLS; }
            float val = (cc < NFEAT) ? s[vv * REC + cc] : s_de[vv] * esc;
            r[j] = val * s_inv[vv];
        }
        ((float4*)(out + NVOX + (size_t)vb * NCLS))[tid] = make_float4(r[0], r[1], r[2], r[3]);
    } else if (tid < FB_VOX * NCLS / 4 + FB_VOX / 4) {
        // density: 16 float4 stores
        int q = tid - FB_VOX * NCLS / 4;
        ((float4*)(out + vb))[q] = make_float4(s_gd[4 * q + 0], s_gd[4 * q + 1],
                                               s_gd[4 * q + 2], s_gd[4 * q + 3]);
    }
}

extern "C" void kernel_launch(void* const* d_in, const int* in_sizes, int n_in,
                              void* d_out, int out_size)
{
    const float* means  = (const float*)d_in[0];
    const float* opac   = (const float*)d_in[1];
    const float* feats  = (const float*)d_in[2];
    const float* scales = (const float*)d_in[3];
    const float* rots   = (const float*)d_in[4];
    const float* es     = (const float*)d_in[5];
    float* out = (float*)d_out;

    int ngauss = in_sizes[0] / 3;

    // zero the scratch accumulator (graph-capturable memset node)
    void* sptr = nullptr;
    cudaGetSymbolAddress(&sptr, g_scratch);
    cudaMemsetAsync(sptr, 0, sizeof(float) * (size_t)NVOX * REC, 0);

    gv_splat_kernel<<<(ngauss + 3) / 4, 128>>>(means, opac, feats, scales, rots, ngauss);

    gv_finalize_kernel<<<NVOX / FB_VOX, FB_THR>>>(out, es);
}

// round 10
// speedup vs baseline: 2.8652x; 1.0086x over previous
#include <cuda_runtime.h>

#define GH 200
#define GW 200
#define GD 16
#define NVOX (GH * GW * GD)      // 640000
#define NCLS 18
#define NFEAT 17
#define KT 10
#define VOXSZ 0.4f

#define TS 4                      // tile is TS x TS x GD voxels
#define TGX (GH / TS)             // 50
#define TGY (GW / TS)             // 50
#define NTILE (TGX * TGY)         // 2500
#define CAP 1024                  // max gaussians per tile (avg ~20 for uniform data)
#define MAXG 16384
#define PSTR 40                   // floats per gaussian param record (160B)

// per-tile gaussian lists + preprocessed per-gaussian params
__device__ int g_cnt[NTILE];
__device__ int g_ids[NTILE * CAP];
// slots: 0..3 m00,m11,m22,m01 | 4..7 m02,m12,mx,my | 8..11 mz,op,thr,f16
//        12..15 bxlo,bylo,bzlo,bxhi | 16..19 byhi,bzhi,pad,pad | 20..35 f0..f15
__device__ __align__(16) float g_par[(size_t)MAXG * PSTR];

__global__ __launch_bounds__(256) void gv_prep_kernel(
    const float* __restrict__ means,
    const float* __restrict__ opac,
    const float* __restrict__ feats,
    const float* __restrict__ scales,
    const float* __restrict__ rots,
    int ngauss)
{
    int n = blockIdx.x * 256 + threadIdx.x;
    if (n >= ngauss || n >= MAXG) return;

    const float lox = -40.f, loy = -40.f, loz = -1.f;
    const float hix =  40.f, hiy =  40.f, hiz =  5.4f;

    float mx = means[3 * n + 0];
    float my = means[3 * n + 1];
    float mz = means[3 * n + 2];

    float qw = rots[4 * n + 0];
    float qx = rots[4 * n + 1];
    float qy = rots[4 * n + 2];
    float qz = rots[4 * n + 3];
    float qn = rsqrtf(qw * qw + qx * qx + qy * qy + qz * qz);
    qw *= qn; qx *= qn; qy *= qn; qz *= qn;

    float r00 = 1.f - 2.f * (qy * qy + qz * qz);
    float r01 = 2.f * (qx * qy - qw * qz);
    float r02 = 2.f * (qx * qz + qw * qy);
    float r10 = 2.f * (qx * qy + qw * qz);
    float r11 = 1.f - 2.f * (qx * qx + qz * qz);
    float r12 = 2.f * (qy * qz - qw * qx);
    float r20 = 2.f * (qx * qz - qw * qy);
    float r21 = 2.f * (qy * qz + qw * qx);
    float r22 = 1.f - 2.f * (qx * qx + qy * qy);

    float s0 = scales[3 * n + 0];
    float s1 = scales[3 * n + 1];
    float s2 = scales[3 * n + 2];
    float i0 = 1.f / (s0 * s0);
    float i1 = 1.f / (s1 * s1);
    float i2 = 1.f / (s2 * s2);

    // cov_inv = R diag(1/s^2) R^T (symmetric), cross terms pre-doubled
    float m00 = r00 * r00 * i0 + r01 * r01 * i1 + r02 * r02 * i2;
    float m11 = r10 * r10 * i0 + r11 * r11 * i1 + r12 * r12 * i2;
    float m22 = r20 * r20 * i0 + r21 * r21 * i1 + r22 * r22 * i2;
    float m01 = 2.f * (r00 * r10 * i0 + r01 * r11 * i1 + r02 * r12 * i2);
    float m02 = 2.f * (r00 * r20 * i0 + r01 * r21 * i1 + r02 * r22 * i2);
    float m12 = 2.f * (r10 * r20 * i0 + r11 * r21 * i1 + r12 * r22 * i2);

    float sigx = sqrtf(r00 * r00 * s0 * s0 + r01 * r01 * s1 * s1 + r02 * r02 * s2 * s2);
    float sigy = sqrtf(r10 * r10 * s0 * s0 + r11 * r11 * s1 * s1 + r12 * r12 * s2 * s2);
    float sigz = sqrtf(r20 * r20 * s0 * s0 + r21 * r21 * s1 * s1 + r22 * r22 * s2 * s2);

    float blox = fminf(fmaxf(mx - 3.f * sigx, lox), hix);
    float bloy = fminf(fmaxf(my - 3.f * sigy, loy), hiy);
    float bloz = fminf(fmaxf(mz - 3.f * sigz, loz), hiz);
    float bhix = fminf(fmaxf(mx + 3.f * sigx, lox), hix);
    float bhiy = fminf(fmaxf(my + 3.f * sigy, loy), hiy);
    float bhiz = fminf(fmaxf(mz + 3.f * sigz, loz), hiz);

    bool valid =
        ((blox > lox) || (bhix > lox)) && ((blox < hix) || (bhix < hix)) &&
        ((bloy > loy) || (bhiy > loy)) && ((bloy < hiy) || (bhiy < hiy)) &&
        ((bloz > loz) || (bhiz > loz)) && ((bloz < hiz) || (bhiz < hiz));
    if (!valid) return;

    int ilox = (int)((blox - lox) / VOXSZ);
    int iloy = (int)((bloy - loy) / VOXSZ);
    int iloz = (int)((bloz - loz) / VOXSZ);
    int ihix = (int)((bhix - lox) / VOXSZ);
    int ihiy = (int)((bhiy - loy) / VOXSZ);
    int ihiz = (int)((bhiz - loz) / VOXSZ);

    int exi = min(min(ihix, ilox + KT - 1), GH - 1);
    int eyi = min(min(ihiy, iloy + KT - 1), GW - 1);
    int ezi = min(min(ihiz, iloz + KT - 1), GD - 1);
    if (exi < ilox || eyi < iloy || ezi < iloz) return;

    float op = opac[n];
    // dens > 1e-7  <=>  maha < 2*ln(op*1e7); op<=1e-7 -> thr<=0 -> never passes
    float thr = 2.f * __logf(op * 1e7f);

    float* P = g_par + (size_t)n * PSTR;
    P[0] = m00; P[1] = m11; P[2] = m22; P[3] = m01;
    P[4] = m02; P[5] = m12; P[6] = mx;  P[7] = my;
    P[8] = mz;  P[9] = op;  P[10] = thr; P[11] = feats[n * NFEAT + 16];
    P[12] = (float)ilox; P[13] = (float)iloy; P[14] = (float)iloz; P[15] = (float)exi;
    P[16] = (float)eyi;  P[17] = (float)ezi;  P[18] = 0.f; P[19] = 0.f;
#pragma unroll
    for (int c = 0; c < 16; c++) P[20 + c] = feats[n * NFEAT + c];

    // append to every xy tile the voxel box overlaps
    int tx0 = ilox / TS, tx1 = exi / TS;
    int ty0 = iloy / TS, ty1 = eyi / TS;
    for (int tx = tx0; tx <= tx1; tx++)
        for (int ty = ty0; ty <= ty1; ty++) {
            int t = tx * TGY + ty;
            int s = atomicAdd(&g_cnt[t], 1);
            if (s < CAP) g_ids[t * CAP + s] = n;
        }
}

__global__ __launch_bounds__(256) void gv_gather_kernel(
    float* __restrict__ out,
    const float* __restrict__ empty_scalar)
{
    __shared__ float sf[TS * TS * GD * NCLS];   // 4608 floats = 18.4KB

    int tile = blockIdx.x;
    int tx = tile / TGY;
    int ty = tile - tx * TGY;

    int tid = threadIdx.x;
    int lx = tid >> 6;           // 0..3
    int ly = (tid >> 4) & 3;     // 0..3
    int lz = tid & 15;           // 0..15
    int vi = tx * TS + lx;
    int vj = ty * TS + ly;
    int vk = lz;

    float cx = (vi + 0.5f) * VOXSZ - 40.f;
    float cy = (vj + 0.5f) * VOXSZ - 40.f;
    float cz = (vk + 0.5f) * VOXSZ - 1.f;
    float viF = (float)vi, vjF = (float)vj, vkF = (float)vk;

    float acc[NFEAT];
#pragma unroll
    for (int c = 0; c < NFEAT; c++) acc[c] = 0.f;
    float accd = 0.f;

    int cnt = min(g_cnt[tile], CAP);
    const int* ids = g_ids + tile * CAP;

    for (int s = 0; s < cnt; s++) {
        int n = ids[s];
        const float4* P = (const float4*)(g_par + (size_t)n * PSTR);
        float4 p0 = __ldg(P + 0);   // m00 m11 m22 m01
        float4 p1 = __ldg(P + 1);   // m02 m12 mx  my
        float4 p2 = __ldg(P + 2);   // mz  op  thr f16
        float4 p3 = __ldg(P + 3);   // bxlo bylo bzlo bxhi
        float4 p4 = __ldg(P + 4);   // byhi bzhi - -

        bool inb = (viF >= p3.x) & (vjF >= p3.y) & (vkF >= p3.z)
                 & (viF <= p3.w) & (vjF <= p4.x) & (vkF <= p4.y);

        float dx = cx - p1.z;
        float dy = cy - p1.w;
        float dz = cz - p2.x;
        float maha = p0.x * dx * dx + p0.y * dy * dy + p0.z * dz * dz
                   + p0.w * dx * dy + p1.x * dx * dz + p1.y * dy * dz;

        if (inb && maha < p2.z) {
            float dens = p2.y * __expf(-0.5f * maha);
            accd += dens;
            float4 f0 = __ldg(P + 5);
            float4 f1 = __ldg(P + 6);
            float4 f2 = __ldg(P + 7);
            float4 f3 = __ldg(P + 8);
            acc[0]  += dens * f0.x;  acc[1]  += dens * f0.y;
            acc[2]  += dens * f0.z;  acc[3]  += dens * f0.w;
            acc[4]  += dens * f1.x;  acc[5]  += dens * f1.y;
            acc[6]  += dens * f1.z;  acc[7]  += dens * f1.w;
            acc[8]  += dens * f2.x;  acc[9]  += dens * f2.y;
            acc[10] += dens * f2.z;  acc[11] += dens * f2.w;
            acc[12] += dens * f3.x;  acc[13] += dens * f3.y;
            acc[14] += dens * f3.z;  acc[15] += dens * f3.w;
            acc[16] += dens * p2.w;
            // class 17 contribution is identically zero
        }
    }

    // empty gaussian: mean (0,0,2.2), inv cov = diag(1/range^2), range (80,80,6.4)
    float ex = cx * (1.f / 80.f);
    float ey = cy * (1.f / 80.f);
    float ez = (cz - 2.2f) * (1.f / 6.4f);
    float dens_e = __expf(-0.5f * (ex * ex + ey * ey + ez * ez));

    float gd  = accd + dens_e;
    float inv = __fdividef(1.f, fmaxf(gd, 1e-6f));

    int flat = (vi * GW + vj) * GD + vk;
    out[flat] = gd;   // 16-float contiguous z-runs -> coalesced enough

    // stage normalized features: column-major contiguous runs of 288 floats
    float esc = empty_scalar[0];
    int col = tid >> 4;                 // lx*4+ly
    float* sc = sf + col * (GD * NCLS) + lz * NCLS;
#pragma unroll
    for (int c = 0; c < NFEAT; c++) sc[c] = acc[c] * inv;
    sc[NFEAT] = dens_e * esc * inv;
    __syncthreads();

    // write 16 columns x 288 floats = 1152 float4s, coalesced per column run
    const float4* sf4 = (const float4*)sf;
    for (int idx = tid; idx < TS * TS * GD * NCLS / 4; idx += 256) {
        int c = idx / (GD * NCLS / 4);          // column 0..15
        int w = idx - c * (GD * NCLS / 4);      // float4 within column run
        int cvi = tx * TS + (c >> 2);
        int cvj = ty * TS + (c & 3);
        size_t base = (size_t)NVOX + (size_t)(cvi * GW + cvj) * GD * NCLS;
        ((float4*)(out + base))[w] = sf4[idx];
    }
}

extern "C" void kernel_launch(void* const* d_in, const int* in_sizes, int n_in,
                              void* d_out, int out_size)
{
    const float* means  = (const float*)d_in[0];
    const float* opac   = (const float*)d_in[1];
    const float* feats  = (const float*)d_in[2];
    const float* scales = (const float*)d_in[3];
    const float* rots   = (const float*)d_in[4];
    const float* es     = (const float*)d_in[5];
    float* out = (float*)d_out;

    int ngauss = in_sizes[0] / 3;

    void* cptr = nullptr;
    cudaGetSymbolAddress(&cptr, g_cnt);
    cudaMemsetAsync(cptr, 0, sizeof(int) * NTILE, 0);

    gv_prep_kernel<<<(ngauss + 255) / 256, 256>>>(means, opac, feats, scales, rots, ngauss);

    gv_gather_kernel<<<NTILE, 256>>>(out, es);
}

// round 13
// speedup vs baseline: 4.3601x; 1.5217x over previous
#include <cuda_runtime.h>

#define GH 200
#define GW 200
#define GD 16
#define NVOX (GH * GW * GD)      // 640000
#define NCLS 18
#define NFEAT 17
#define KT 10
#define VOXSZ 0.4f

#define TS 4                      // tile is TS x TS x GD voxels
#define TGX (GH / TS)             // 50
#define TGY (GW / TS)             // 50
#define NTILE (TGX * TGY)         // 2500
#define CAP 1024                  // max gaussians per tile
#define MAXG 16384
#define PSTR 40                   // floats per gaussian param record (160B)
#define CHUNK 64                  // gaussians staged to smem per pass
#define RECQ 9                    // float4s used per record

// per-tile gaussian lists + preprocessed per-gaussian params
__device__ int g_cnt[NTILE];
__device__ int g_ids[NTILE * CAP];
// slots: 0..3 m00,m11,m22,m01 | 4..7 m02,m12,mx,my | 8..11 mz,op,thr,f16
//        12..15 bxlo,bylo,bzlo,bxhi | 16..19 byhi,bzhi,pad,pad | 20..35 f0..f15
__device__ __align__(16) float g_par[(size_t)MAXG * PSTR];

__global__ __launch_bounds__(256) void gv_prep_kernel(
    const float* __restrict__ means,
    const float* __restrict__ opac,
    const float* __restrict__ feats,
    const float* __restrict__ scales,
    const float* __restrict__ rots,
    int ngauss)
{
    int n = blockIdx.x * 256 + threadIdx.x;
    if (n >= ngauss || n >= MAXG) return;

    const float lox = -40.f, loy = -40.f, loz = -1.f;
    const float hix =  40.f, hiy =  40.f, hiz =  5.4f;

    float mx = means[3 * n + 0];
    float my = means[3 * n + 1];
    float mz = means[3 * n + 2];

    float qw = rots[4 * n + 0];
    float qx = rots[4 * n + 1];
    float qy = rots[4 * n + 2];
    float qz = rots[4 * n + 3];
    float qn = rsqrtf(qw * qw + qx * qx + qy * qy + qz * qz);
    qw *= qn; qx *= qn; qy *= qn; qz *= qn;

    float r00 = 1.f - 2.f * (qy * qy + qz * qz);
    float r01 = 2.f * (qx * qy - qw * qz);
    float r02 = 2.f * (qx * qz + qw * qy);
    float r10 = 2.f * (qx * qy + qw * qz);
    float r11 = 1.f - 2.f * (qx * qx + qz * qz);
    float r12 = 2.f * (qy * qz - qw * qx);
    float r20 = 2.f * (qx * qz - qw * qy);
    float r21 = 2.f * (qy * qz + qw * qx);
    float r22 = 1.f - 2.f * (qx * qx + qy * qy);

    float s0 = scales[3 * n + 0];
    float s1 = scales[3 * n + 1];
    float s2 = scales[3 * n + 2];
    float i0 = 1.f / (s0 * s0);
    float i1 = 1.f / (s1 * s1);
    float i2 = 1.f / (s2 * s2);

    // cov_inv = R diag(1/s^2) R^T (symmetric), cross terms pre-doubled
    float m00 = r00 * r00 * i0 + r01 * r01 * i1 + r02 * r02 * i2;
    float m11 = r10 * r10 * i0 + r11 * r11 * i1 + r12 * r12 * i2;
    float m22 = r20 * r20 * i0 + r21 * r21 * i1 + r22 * r22 * i2;
    float m01 = 2.f * (r00 * r10 * i0 + r01 * r11 * i1 + r02 * r12 * i2);
    float m02 = 2.f * (r00 * r20 * i0 + r01 * r21 * i1 + r02 * r22 * i2);
    float m12 = 2.f * (r10 * r20 * i0 + r11 * r21 * i1 + r12 * r22 * i2);

    float sigx = sqrtf(r00 * r00 * s0 * s0 + r01 * r01 * s1 * s1 + r02 * r02 * s2 * s2);
    float sigy = sqrtf(r10 * r10 * s0 * s0 + r11 * r11 * s1 * s1 + r12 * r12 * s2 * s2);
    float sigz = sqrtf(r20 * r20 * s0 * s0 + r21 * r21 * s1 * s1 + r22 * r22 * s2 * s2);

    float blox = fminf(fmaxf(mx - 3.f * sigx, lox), hix);
    float bloy = fminf(fmaxf(my - 3.f * sigy, loy), hiy);
    float bloz = fminf(fmaxf(mz - 3.f * sigz, loz), hiz);
    float bhix = fminf(fmaxf(mx + 3.f * sigx, lox), hix);
    float bhiy = fminf(fmaxf(my + 3.f * sigy, loy), hiy);
    float bhiz = fminf(fmaxf(mz + 3.f * sigz, loz), hiz);

    bool valid =
        ((blox > lox) || (bhix > lox)) && ((blox < hix) || (bhix < hix)) &&
        ((bloy > loy) || (bhiy > loy)) && ((bloy < hiy) || (bhiy < hiy)) &&
        ((bloz > loz) || (bhiz > loz)) && ((bloz < hiz) || (bhiz < hiz));
    if (!valid) return;

    int ilox = (int)((blox - lox) / VOXSZ);
    int iloy = (int)((bloy - loy) / VOXSZ);
    int iloz = (int)((bloz - loz) / VOXSZ);
    int ihix = (int)((bhix - lox) / VOXSZ);
    int ihiy = (int)((bhiy - loy) / VOXSZ);
    int ihiz = (int)((bhiz - loz) / VOXSZ);

    int exi = min(min(ihix, ilox + KT - 1), GH - 1);
    int eyi = min(min(ihiy, iloy + KT - 1), GW - 1);
    int ezi = min(min(ihiz, iloz + KT - 1), GD - 1);
    if (exi < ilox || eyi < iloy || ezi < iloz) return;

    float op = opac[n];
    // dens > 1e-7  <=>  maha < 2*ln(op*1e7); op<=1e-7 -> thr<=0 -> never passes
    float thr = 2.f * __logf(op * 1e7f);

    float* P = g_par + (size_t)n * PSTR;
    P[0] = m00; P[1] = m11; P[2] = m22; P[3] = m01;
    P[4] = m02; P[5] = m12; P[6] = mx;  P[7] = my;
    P[8] = mz;  P[9] = op;  P[10] = thr; P[11] = feats[n * NFEAT + 16];
    P[12] = (float)ilox; P[13] = (float)iloy; P[14] = (float)iloz; P[15] = (float)exi;
    P[16] = (float)eyi;  P[17] = (float)ezi;  P[18] = 0.f; P[19] = 0.f;
#pragma unroll
    for (int c = 0; c < 16; c++) P[20 + c] = feats[n * NFEAT + c];

    // append to every xy tile the voxel box overlaps
    int tx0 = ilox / TS, tx1 = exi / TS;
    int ty0 = iloy / TS, ty1 = eyi / TS;
    for (int tx = tx0; tx <= tx1; tx++)
        for (int ty = ty0; ty <= ty1; ty++) {
            int t = tx * TGY + ty;
            int s = atomicAdd(&g_cnt[t], 1);
            if (s < CAP) g_ids[t * CAP + s] = n;
        }
}

__global__ __launch_bounds__(256) void gv_gather_kernel(
    float* __restrict__ out,
    const float* __restrict__ empty_scalar)
{
    // one buffer, two lives: main loop = staged params (CHUNK*RECQ = 576 float4),
    // epilogue = normalized features (1152 float4). Barriers separate the uses.
    __shared__ float4 sbuf[TS * TS * GD * NCLS / 4];   // 1152 float4 = 18.4KB

    int tile = blockIdx.x;
    int tx = tile / TGY;
    int ty = tile - tx * TGY;

    int tid = threadIdx.x;
    int lx = tid >> 6;           // 0..3
    int ly = (tid >> 4) & 3;     // 0..3
    int lz = tid & 15;           // 0..15
    int vi = tx * TS + lx;
    int vj = ty * TS + ly;
    int vk = lz;

    float cx = (vi + 0.5f) * VOXSZ - 40.f;
    float cy = (vj + 0.5f) * VOXSZ - 40.f;
    float cz = (vk + 0.5f) * VOXSZ - 1.f;
    float viF = (float)vi, vjF = (float)vj, vkF = (float)vk;

    float acc[NFEAT];
#pragma unroll
    for (int c = 0; c < NFEAT; c++) acc[c] = 0.f;
    float accd = 0.f;

    int cnt = min(g_cnt[tile], CAP);
    const int* ids = g_ids + tile * CAP;

    for (int base = 0; base < cnt; base += CHUNK) {
        int m = min(CHUNK, cnt - base);

        // cooperative coalesced stage-in: m records x 9 float4s
        for (int i = tid; i < m * RECQ; i += 256) {
            int s = i / RECQ;
            int q = i - s * RECQ;
            int n = ids[base + s];
            sbuf[i] = ((const float4*)(g_par + (size_t)n * PSTR))[q];
        }
        __syncthreads();

        for (int s = 0; s < m; s++) {
            const float4* P = sbuf + s * RECQ;   // LDS broadcast, conflict-free
            float4 p0 = P[0];   // m00 m11 m22 m01
            float4 p1 = P[1];   // m02 m12 mx  my
            float4 p2 = P[2];   // mz  op  thr f16
            float4 p3 = P[3];   // bxlo bylo bzlo bxhi
            float4 p4 = P[4];   // byhi bzhi - -

            bool inb = (viF >= p3.x) & (vjF >= p3.y) & (vkF >= p3.z)
                     & (viF <= p3.w) & (vjF <= p4.x) & (vkF <= p4.y);

            float dx = cx - p1.z;
            float dy = cy - p1.w;
            float dz = cz - p2.x;
            float maha = p0.x * dx * dx + p0.y * dy * dy + p0.z * dz * dz
                       + p0.w * dx * dy + p1.x * dx * dz + p1.y * dy * dz;

            if (inb && maha < p2.z) {
                float dens = p2.y * __expf(-0.5f * maha);
                accd += dens;
                float4 f0 = P[5];
                float4 f1 = P[6];
                float4 f2 = P[7];
                float4 f3 = P[8];
                acc[0]  += dens * f0.x;  acc[1]  += dens * f0.y;
                acc[2]  += dens * f0.z;  acc[3]  += dens * f0.w;
                acc[4]  += dens * f1.x;  acc[5]  += dens * f1.y;
                acc[6]  += dens * f1.z;  acc[7]  += dens * f1.w;
                acc[8]  += dens * f2.x;  acc[9]  += dens * f2.y;
                acc[10] += dens * f2.z;  acc[11] += dens * f2.w;
                acc[12] += dens * f3.x;  acc[13] += dens * f3.y;
                acc[14] += dens * f3.z;  acc[15] += dens * f3.w;
                acc[16] += dens * p2.w;
                // class 17 contribution is identically zero
            }
        }
        __syncthreads();   // protect sbuf before next stage-in / epilogue reuse
    }

    // empty gaussian: mean (0,0,2.2), inv cov = diag(1/range^2), range (80,80,6.4)
    float ex = cx * (1.f / 80.f);
    float ey = cy * (1.f / 80.f);
    float ez = (cz - 2.2f) * (1.f / 6.4f);
    float dens_e = __expf(-0.5f * (ex * ex + ey * ey + ez * ez));

    float gd  = accd + dens_e;
    float inv = __fdividef(1.f, fmaxf(gd, 1e-6f));

    int flat = (vi * GW + vj) * GD + vk;
    out[flat] = gd;

    // stage normalized features: column-major contiguous runs of 288 floats
    float esc = empty_scalar[0];
    float* sf = (float*)sbuf;
    int col = tid >> 4;                 // lx*4+ly
    float* sc = sf + col * (GD * NCLS) + lz * NCLS;
#pragma unroll
    for (int c = 0; c < NFEAT; c++) sc[c] = acc[c] * inv;
    sc[NFEAT] = dens_e * esc * inv;
    __syncthreads();

    // write 16 columns x 288 floats = 1152 float4s, coalesced per column run
    for (int idx = tid; idx < TS * TS * GD * NCLS / 4; idx += 256) {
        int c = idx / (GD * NCLS / 4);          // column 0..15
        int w = idx - c * (GD * NCLS / 4);      // float4 within column run
        int cvi = tx * TS + (c >> 2);
        int cvj = ty * TS + (c & 3);
        size_t base = (size_t)NVOX + (size_t)(cvi * GW + cvj) * GD * NCLS;
        ((float4*)(out + base))[w] = sbuf[idx];
    }
}

extern "C" void kernel_launch(void* const* d_in, const int* in_sizes, int n_in,
                              void* d_out, int out_size)
{
    const float* means  = (const float*)d_in[0];
    const float* opac   = (const float*)d_in[1];
    const float* feats  = (const float*)d_in[2];
    const float* scales = (const float*)d_in[3];
    const float* rots   = (const float*)d_in[4];
    const float* es     = (const float*)d_in[5];
    float* out = (float*)d_out;

    int ngauss = in_sizes[0] / 3;

    void* cptr = nullptr;
    cudaGetSymbolAddress(&cptr, g_cnt);
    cudaMemsetAsync(cptr, 0, sizeof(int) * NTILE, 0);

    gv_prep_kernel<<<(ngauss + 255) / 256, 256>>>(means, opac, feats, scales, rots, ngauss);

    gv_gather_kernel<<<NTILE, 256>>>(out, es);
}